// round 16
// baseline (speedup 1.0000x reference)
#include <cuda_runtime.h>
#include <cuda_fp16.h>
#include <cstdint>
#include <cstddef>

#define B_ 2
#define T_ 4096
#define C_ 768
#define H_ 12
#define D_ 64
#define M_ (B_*T_)          // 8192
#define N_QKV (3*C_)        // 2304
// softmax scale folded with log2(e) so we can use ex2
#define QSCALE (0.125f * 1.4426950408889634f)

// fp16 scratch (allocation-free requirement -> __device__ globals)
__device__ __half g_xh[(size_t)M_ * C_];
__device__ __half g_wqkvh[(size_t)C_ * N_QKV];
__device__ __half g_wouth[(size_t)C_ * C_];
__device__ __half g_qkvh[(size_t)M_ * N_QKV];   // Q part pre-scaled by QSCALE
__device__ __half g_attnh[(size_t)M_ * C_];

// ---------------------------------------------------------------------------
// Helpers
// ---------------------------------------------------------------------------
__device__ __forceinline__ void mma_f16(float* c, const uint32_t* a,
                                        uint32_t b0, uint32_t b1) {
    asm volatile(
        "mma.sync.aligned.m16n8k16.row.col.f32.f16.f16.f32 "
        "{%0,%1,%2,%3},{%4,%5,%6,%7},{%8,%9},{%0,%1,%2,%3};"
        : "+f"(c[0]), "+f"(c[1]), "+f"(c[2]), "+f"(c[3])
        : "r"(a[0]), "r"(a[1]), "r"(a[2]), "r"(a[3]), "r"(b0), "r"(b1));
}

__device__ __forceinline__ void ldsm_x4(uint32_t& r0, uint32_t& r1,
                                        uint32_t& r2, uint32_t& r3,
                                        uint32_t addr) {
    asm volatile(
        "ldmatrix.sync.aligned.m8n8.x4.shared.b16 {%0,%1,%2,%3}, [%4];"
        : "=r"(r0), "=r"(r1), "=r"(r2), "=r"(r3) : "r"(addr));
}

__device__ __forceinline__ void ldsm_x4_trans(uint32_t& r0, uint32_t& r1,
                                              uint32_t& r2, uint32_t& r3,
                                              uint32_t addr) {
    asm volatile(
        "ldmatrix.sync.aligned.m8n8.x4.trans.shared.b16 {%0,%1,%2,%3}, [%4];"
        : "=r"(r0), "=r"(r1), "=r"(r2), "=r"(r3) : "r"(addr));
}

__device__ __forceinline__ uint32_t pack_h2(float lo, float hi) {
    __half2 h = __floats2half2_rn(lo, hi);
    return *reinterpret_cast<uint32_t*>(&h);
}

__device__ __forceinline__ float fast_exp2(float x) {
    float r;
    asm("ex2.approx.ftz.f32 %0, %1;" : "=f"(r) : "f"(x));
    return r;
}

// packed fp16 helpers (softmax fast path)
__device__ __forceinline__ uint32_t hsub2(uint32_t a, uint32_t b) {
    uint32_t r;
    asm("sub.f16x2 %0, %1, %2;" : "=r"(r) : "r"(a), "r"(b));
    return r;
}
__device__ __forceinline__ uint32_t hex2_h2(uint32_t x) {
    uint32_t r;
    asm("ex2.approx.f16x2 %0, %1;" : "=r"(r) : "r"(x));
    return r;
}

__device__ __forceinline__ uint32_t smem_u32(const void* p) {
    return (uint32_t)__cvta_generic_to_shared(p);
}
// L1-preserving async copy (NOT .cg — the round-4 lesson)
__device__ __forceinline__ void cp_async16_ca(uint32_t dst, const void* src) {
    asm volatile("cp.async.ca.shared.global [%0], [%1], 16;"
                 :: "r"(dst), "l"(src));
}
__device__ __forceinline__ void cp_commit() {
    asm volatile("cp.async.commit_group;");
}
__device__ __forceinline__ void cp_wait0() {
    asm volatile("cp.async.wait_group 0;");
}

// ---------------------------------------------------------------------------
// Fused fp32 -> fp16 conversion for all three tensors (one launch)
// ---------------------------------------------------------------------------
__global__ void __launch_bounds__(256)
cvt3_f32_f16(const float* __restrict__ a, __half* __restrict__ oa, int na4,
             const float* __restrict__ b, __half* __restrict__ ob, int nb4,
             const float* __restrict__ c, __half* __restrict__ oc, int nc4)
{
    int i = blockIdx.x * blockDim.x + threadIdx.x;
    const float* in;
    __half* out;
    int off;
    if (i < na4)                  { in = a; out = oa; off = i; }
    else if (i < na4 + nb4)       { in = b; out = ob; off = i - na4; }
    else if (i < na4 + nb4 + nc4) { in = c; out = oc; off = i - na4 - nb4; }
    else return;

    float4 v = reinterpret_cast<const float4*>(in)[off];
    __half2 h0 = __floats2half2_rn(v.x, v.y);
    __half2 h1 = __floats2half2_rn(v.z, v.w);
    uint2 u;
    u.x = *reinterpret_cast<uint32_t*>(&h0);
    u.y = *reinterpret_cast<uint32_t*>(&h1);
    reinterpret_cast<uint2*>(out)[off] = u;
}

// ---------------------------------------------------------------------------
// fp16-in tensor-core GEMM with bias (round-9 proven version):
// C[M,N] = A[M,K] @ B[K,N] + bias[N]
// BM=BN=128, BK=32, 256 threads (8 warps), warp tile 64x32 (m16n8k16).
// 2-stage smem double buffer + register prefetch, 2 CTAs/SM.
// ---------------------------------------------------------------------------
template<bool HALF_OUT>
__global__ void __launch_bounds__(256, 2)
gemm_h_kernel(const __half* __restrict__ A, const __half* __restrict__ B,
              const float* __restrict__ bias, void* __restrict__ Cout,
              int M, int N, int K, int qcols, float qsc)
{
    __shared__ __half As[2][128][40];   // 20480 B
    __shared__ __half Bs[2][32][136];   // 17408 B

    const int tid = threadIdx.x;
    const int wid = tid >> 5;
    const int lane = tid & 31;
    const int g = lane >> 2;
    const int t4 = lane & 3;
    const int wm = wid >> 2;
    const int wn = wid & 3;
    const int bx = blockIdx.x, by = blockIdx.y;
    const int mrow = lane & 7;
    const int mid  = lane >> 3;

    const uint32_t abase = smem_u32(
        &As[0][wm * 64 + (mid & 1) * 8 + mrow][(mid >> 1) * 8]);
    const uint32_t bbase = smem_u32(
        &Bs[0][(mid & 1) * 8 + mrow][wn * 32 + (mid >> 1) * 8]);
    const uint32_t a_ststride = 128 * 40 * 2;
    const uint32_t b_ststride = 32 * 136 * 2;

    const int ar = tid >> 2;            // rows ar, ar+64
    const int ach = tid & 3;
    const int br = tid >> 4;            // rows br, br+16
    const int bch = tid & 15;

    const __half* aG = A + (size_t)(by * 128 + ar) * K + ach * 8;
    const __half* bG = B + (size_t)br * N + bx * 128 + bch * 8;
    const size_t aRow64 = (size_t)64 * K;
    const size_t bRow16 = (size_t)16 * N;

    uint4 pa0, pa1, pb0, pb1;
    auto ldg_slab = [&](int k0) {
        pa0 = *reinterpret_cast<const uint4*>(aG + k0);
        pa1 = *reinterpret_cast<const uint4*>(aG + aRow64 + k0);
        pb0 = *reinterpret_cast<const uint4*>(bG + (size_t)k0 * N);
        pb1 = *reinterpret_cast<const uint4*>(bG + (size_t)k0 * N + bRow16);
    };
    auto sts_slab = [&](int st) {
        *reinterpret_cast<uint4*>(&As[st][ar][ach * 8])      = pa0;
        *reinterpret_cast<uint4*>(&As[st][ar + 64][ach * 8]) = pa1;
        *reinterpret_cast<uint4*>(&Bs[st][br][bch * 8])      = pb0;
        *reinterpret_cast<uint4*>(&Bs[st][br + 16][bch * 8]) = pb1;
    };

    float acc[4][4][4];
    #pragma unroll
    for (int mt = 0; mt < 4; mt++)
        #pragma unroll
        for (int nt = 0; nt < 4; nt++)
            #pragma unroll
            for (int i = 0; i < 4; i++) acc[mt][nt][i] = 0.f;

    const int steps = K >> 5;
    ldg_slab(0);
    sts_slab(0);
    __syncthreads();

    for (int s = 0; s < steps; s++) {
        if (s + 1 < steps) ldg_slab((s + 1) << 5);

        const uint32_t ab = abase + (uint32_t)(s & 1) * a_ststride;
        const uint32_t bb = bbase + (uint32_t)(s & 1) * b_ststride;
        #pragma unroll
        for (int kk = 0; kk < 32; kk += 16) {
            uint32_t afr[4][4], bfr[4][2];
            #pragma unroll
            for (int mt = 0; mt < 4; mt++)
                ldsm_x4(afr[mt][0], afr[mt][1], afr[mt][2], afr[mt][3],
                        ab + (uint32_t)(mt * 16 * 40 + kk) * 2);
            #pragma unroll
            for (int p = 0; p < 2; p++) {
                uint32_t r0, r1, r2, r3;
                ldsm_x4_trans(r0, r1, r2, r3,
                              bb + (uint32_t)(kk * 136 + p * 16) * 2);
                bfr[2 * p][0] = r0; bfr[2 * p][1] = r1;
                bfr[2 * p + 1][0] = r2; bfr[2 * p + 1][1] = r3;
            }
            #pragma unroll
            for (int mt = 0; mt < 4; mt++)
                #pragma unroll
                for (int nt = 0; nt < 4; nt++)
                    mma_f16(acc[mt][nt], afr[mt], bfr[nt][0], bfr[nt][1]);
        }

        if (s + 1 < steps) sts_slab((s + 1) & 1);
        __syncthreads();
    }

    // ---- epilogue ----
    float osc = 1.f;
    if (HALF_OUT) osc = (bx * 128 < qcols) ? qsc : 1.f;

    #pragma unroll
    for (int nt = 0; nt < 4; nt++) {
        const int col = bx * 128 + wn * 32 + nt * 8 + 2 * t4;
        const float b0 = bias[col], b1 = bias[col + 1];
        #pragma unroll
        for (int mt = 0; mt < 4; mt++) {
            const int row = by * 128 + wm * 64 + mt * 16 + g;
            if (HALF_OUT) {
                __half* Ch = (__half*)Cout;
                uint32_t v0 = pack_h2((acc[mt][nt][0] + b0) * osc,
                                      (acc[mt][nt][1] + b1) * osc);
                uint32_t v1 = pack_h2((acc[mt][nt][2] + b0) * osc,
                                      (acc[mt][nt][3] + b1) * osc);
                *reinterpret_cast<uint32_t*>(&Ch[(size_t)row * N + col]) = v0;
                *reinterpret_cast<uint32_t*>(&Ch[(size_t)(row + 8) * N + col]) = v1;
            } else {
                float* Cf = (float*)Cout;
                float2 o0 = make_float2(acc[mt][nt][0] + b0, acc[mt][nt][1] + b1);
                float2 o1 = make_float2(acc[mt][nt][2] + b0, acc[mt][nt][3] + b1);
                *reinterpret_cast<float2*>(Cf + (size_t)row * N + col) = o0;
                *reinterpret_cast<float2*>(Cf + (size_t)(row + 8) * N + col) = o1;
            }
        }
    }
}

// ---------------------------------------------------------------------------
// Flash attention (causal), fp16 end-to-end, Bc=128.
// grid = (T/128, B*H), 256 threads (8 warps). Br=128, Bc=128, D=64.
// Dynamic smem: Q[128][72] + K[2][128][72] + V[2][128][72] = 92160 B.
// Per-tile softmax overhead (o-rescale, max-reduce, shfl, sync) halved vs
// Bc=64. Diagonal tile: warp w skips np/kc blocks fully above the causal
// boundary (np > w, kc > w). P fragments built inline (no extra live regs).
// ---------------------------------------------------------------------------
#define QH_HALFS (128 * 72)
#define KV_HALFS (128 * 72)
#define ATTN_SMEM ((QH_HALFS + 4 * KV_HALFS) * 2)

__global__ void __launch_bounds__(256)
attn_mma_kernel(const __half* __restrict__ qkvh, __half* __restrict__ outh)
{
    extern __shared__ __half smh[];
    __half* Qh = smh;                               // [128][72]
    __half* Kh = smh + QH_HALFS;                    // [2][128][72]
    __half* Vh = smh + QH_HALFS + 2 * KV_HALFS;     // [2][128][72]

    const int bh = blockIdx.y;
    const int b = bh / H_;
    const int h = bh % H_;
    const int qtile = gridDim.x - 1 - blockIdx.x;   // big tiles first
    const int tid = threadIdx.x;
    const int w = tid >> 5;
    const int lane = tid & 31;
    const int g = lane >> 2;
    const int t4 = lane & 3;
    const int mrow = lane & 7;
    const int mid  = lane >> 3;

    // ldmatrix bases (stage 0); stage stride in bytes
    const uint32_t kfb = smem_u32(&Kh[((mid >> 1) * 8 + mrow) * 72 + (mid & 1) * 8]);
    const uint32_t vfb = smem_u32(&Vh[((mid & 1) * 8 + mrow) * 72 + (mid >> 1) * 8]);
    const uint32_t kvstride = KV_HALFS * 2;

    // ones-column B fragment: B[k][n]=1 iff n==0 -> nonzero only for g==0
    const uint32_t onesb = (g == 0) ? 0x3C003C00u : 0u;

    // K/V cp.async: 128 rows x 8 chunks per tensor -> 4 chunks/thread each
    auto stage_kv = [&](int kbase, int st) {
        #pragma unroll
        for (int i = 0; i < 4; i++) {
            const int c = tid + i * 256;      // 0..1023
            const int r = c >> 3;             // 0..127
            const int ch = c & 7;
            const __half* src =
                qkvh + (size_t)(b * T_ + kbase + r) * N_QKV + h * D_ + ch * 8;
            cp_async16_ca(smem_u32(&Kh[st * KV_HALFS + r * 72 + ch * 8]), src + C_);
            cp_async16_ca(smem_u32(&Vh[st * KV_HALFS + r * 72 + ch * 8]), src + 2 * C_);
        }
        cp_commit();
    };

    // ---- prologue: issue K/V tile 0, stage Q (plain stores) ----
    stage_kv(0, 0);
    #pragma unroll
    for (int i = 0; i < 4; i++) {
        const int c = tid + i * 256;
        const int r = c >> 3;
        const int ch = c & 7;
        *reinterpret_cast<uint4*>(&Qh[r * 72 + ch * 8]) =
            *reinterpret_cast<const uint4*>(
                qkvh + (size_t)(b * T_ + qtile * 128 + r) * N_QKV + h * D_ + ch * 8);
    }
    __syncthreads();

    // ---- Q fragments: 4 k16-chunks x 4 half2 regs (conflict-free LDS) ----
    uint32_t Qa[4][4];
    {
        const int row = w * 16;
        #pragma unroll
        for (int kc = 0; kc < 4; kc++) {
            const int k0 = kc * 16 + 2 * t4;
            Qa[kc][0] = *reinterpret_cast<const uint32_t*>(&Qh[(row + g) * 72 + k0]);
            Qa[kc][1] = *reinterpret_cast<const uint32_t*>(&Qh[(row + g + 8) * 72 + k0]);
            Qa[kc][2] = *reinterpret_cast<const uint32_t*>(&Qh[(row + g) * 72 + k0 + 8]);
            Qa[kc][3] = *reinterpret_cast<const uint32_t*>(&Qh[(row + g + 8) * 72 + k0 + 8]);
        }
    }

    float o[8][4];
    #pragma unroll
    for (int nt = 0; nt < 8; nt++)
        #pragma unroll
        for (int i = 0; i < 4; i++) o[nt][i] = 0.f;
    float la[4] = {0.f, 0.f, 0.f, 0.f};     // ones-column accumulator (l sums)
    float m0 = -1e30f, m1 = -1e30f;

    const int q0g = qtile * 128 + w * 16 + g;   // own query row (second is +8)
    const int ntiles = qtile + 1;               // 128-wide KV tiles

    for (int kt = 0; kt < ntiles; kt++) {
        const int kbase = kt * 128;
        const bool diag = (kt == ntiles - 1);
        const int blkmax = diag ? w : 7;        // skip blocks above diagonal
        cp_wait0();
        __syncthreads();
        if (kt + 1 < ntiles)
            stage_kv((kt + 1) * 128, (kt + 1) & 1);

        const uint32_t kb = kfb + (uint32_t)(kt & 1) * kvstride;
        const uint32_t vb = vfb + (uint32_t)(kt & 1) * kvstride;

        // ---- S = Q @ K^T (16x128 per warp); K frags via ldmatrix.x4 ----
        float s_[16][4];
        #pragma unroll
        for (int nt = 0; nt < 16; nt++)
            #pragma unroll
            for (int i = 0; i < 4; i++) s_[nt][i] = 0.f;
        #pragma unroll
        for (int kc = 0; kc < 4; kc++) {
            #pragma unroll
            for (int np = 0; np < 8; np++) {
                if (np > blkmax) break;
                uint32_t r0, r1, r2, r3;
                ldsm_x4(r0, r1, r2, r3,
                        kb + (uint32_t)(np * 16 * 72 + kc * 16) * 2);
                mma_f16(s_[2 * np],     Qa[kc], r0, r1);
                mma_f16(s_[2 * np + 1], Qa[kc], r2, r3);
            }
        }

        // ---- causal mask (diagonal tile only) ----
        if (diag) {
            #pragma unroll
            for (int nt = 0; nt < 16; nt++) {
                const int c0 = kbase + nt * 8 + 2 * t4;
                if (c0 > q0g)         s_[nt][0] = -1e30f;
                if (c0 + 1 > q0g)     s_[nt][1] = -1e30f;
                if (c0 > q0g + 8)     s_[nt][2] = -1e30f;
                if (c0 + 1 > q0g + 8) s_[nt][3] = -1e30f;
            }
        }

        // ---- online softmax (base-2), one update per 128 columns ----
        float mx0 = -1e30f, mx1 = -1e30f;
        #pragma unroll
        for (int nt = 0; nt < 16; nt++) {
            mx0 = fmaxf(mx0, fmaxf(s_[nt][0], s_[nt][1]));
            mx1 = fmaxf(mx1, fmaxf(s_[nt][2], s_[nt][3]));
        }
        mx0 = fmaxf(mx0, __shfl_xor_sync(0xffffffff, mx0, 1));
        mx0 = fmaxf(mx0, __shfl_xor_sync(0xffffffff, mx0, 2));
        mx1 = fmaxf(mx1, __shfl_xor_sync(0xffffffff, mx1, 1));
        mx1 = fmaxf(mx1, __shfl_xor_sync(0xffffffff, mx1, 2));
        const float nm0 = fmaxf(m0, mx0), nm1 = fmaxf(m1, mx1);
        const float sc0 = fast_exp2(m0 - nm0), sc1 = fast_exp2(m1 - nm1);
        m0 = nm0; m1 = nm1;

        const uint32_t mh0 = pack_h2(m0, m0);
        const uint32_t mh1 = pack_h2(m1, m1);

        la[0] *= sc0; la[1] *= sc0; la[2] *= sc1; la[3] *= sc1;
        #pragma unroll
        for (int nt = 0; nt < 8; nt++) {
            o[nt][0] *= sc0; o[nt][1] *= sc0;
            o[nt][2] *= sc1; o[nt][3] *= sc1;
        }

        // ---- O += P @ V ; l += P @ ones (P built inline, fp16) ----
        #pragma unroll
        for (int kc = 0; kc < 8; kc++) {
            if (kc > blkmax) break;
            uint32_t pa[4];
            pa[0] = hex2_h2(hsub2(pack_h2(s_[2 * kc][0],     s_[2 * kc][1]),     mh0));
            pa[1] = hex2_h2(hsub2(pack_h2(s_[2 * kc][2],     s_[2 * kc][3]),     mh1));
            pa[2] = hex2_h2(hsub2(pack_h2(s_[2 * kc + 1][0], s_[2 * kc + 1][1]), mh0));
            pa[3] = hex2_h2(hsub2(pack_h2(s_[2 * kc + 1][2], s_[2 * kc + 1][3]), mh1));
            #pragma unroll
            for (int p = 0; p < 4; p++) {
                uint32_t v0, v1, v2, v3;
                ldsm_x4_trans(v0, v1, v2, v3,
                              vb + (uint32_t)(kc * 16 * 72 + p * 16) * 2);
                mma_f16(o[2 * p],     pa, v0, v1);
                mma_f16(o[2 * p + 1], pa, v2, v3);
            }
            mma_f16(la, pa, onesb, onesb);
        }
    }

    // ---- broadcast l (column 0 lives in t4==0 lanes), normalize, store ----
    const int qlead = lane & 28;       // lane of t4==0 in this quad
    const float l0 = __shfl_sync(0xffffffff, la[0], qlead);
    const float l1 = __shfl_sync(0xffffffff, la[2], qlead);
    const float inv0 = 1.f / l0, inv1 = 1.f / l1;
    const size_t row0 = (size_t)(b * T_ + qtile * 128 + w * 16 + g);
    const size_t row1 = row0 + 8;
    #pragma unroll
    for (int nt = 0; nt < 8; nt++) {
        const int col = h * D_ + nt * 8 + 2 * t4;
        uint32_t v0 = pack_h2(o[nt][0] * inv0, o[nt][1] * inv0);
        uint32_t v1 = pack_h2(o[nt][2] * inv1, o[nt][3] * inv1);
        *reinterpret_cast<uint32_t*>(&outh[row0 * C_ + col]) = v0;
        *reinterpret_cast<uint32_t*>(&outh[row1 * C_ + col]) = v1;
    }
}

// ---------------------------------------------------------------------------
// Launch
// ---------------------------------------------------------------------------
extern "C" void kernel_launch(void* const* d_in, const int* in_sizes, int n_in,
                              void* d_out, int out_size)
{
    const float* x    = (const float*)d_in[0];
    const float* Wqkv = (const float*)d_in[1];
    const float* bqkv = (const float*)d_in[2];
    const float* Wout = (const float*)d_in[3];
    const float* bout = (const float*)d_in[4];
    float* out = (float*)d_out;

    __half *xh, *wqkvh, *wouth, *qkvh, *attnh;
    cudaGetSymbolAddress((void**)&xh,    g_xh);
    cudaGetSymbolAddress((void**)&wqkvh, g_wqkvh);
    cudaGetSymbolAddress((void**)&wouth, g_wouth);
    cudaGetSymbolAddress((void**)&qkvh,  g_qkvh);
    cudaGetSymbolAddress((void**)&attnh, g_attnh);

    cudaFuncSetAttribute(attn_mma_kernel,
                         cudaFuncAttributeMaxDynamicSharedMemorySize, ATTN_SMEM);

    // 0) fp32 -> fp16 conversions (single fused launch)
    {
        const int n0 = M_ * C_ / 4;
        const int n1 = C_ * N_QKV / 4;
        const int n2 = C_ * C_ / 4;
        const int ntot = n0 + n1 + n2;
        cvt3_f32_f16<<<(ntot + 255) / 256, 256>>>(x, xh, n0,
                                                  Wqkv, wqkvh, n1,
                                                  Wout, wouth, n2);
    }

    // 1) QKV projection (fp16 out, Q columns pre-scaled by QSCALE)
    {
        dim3 grid(N_QKV / 128, M_ / 128);
        gemm_h_kernel<true><<<grid, 256>>>(xh, wqkvh, bqkv, qkvh,
                                           M_, N_QKV, C_, C_, (float)QSCALE);
    }
    // 2) Causal attention (flash, fp16 tensor cores, fp16 out, Bc=128)
    {
        dim3 grid(T_ / 128, B_ * H_);
        attn_mma_kernel<<<grid, 256, ATTN_SMEM>>>(qkvh, attnh);
    }
    // 3) Output projection (fp32 out)
    {
        dim3 grid(C_ / 128, M_ / 128);
        gemm_h_kernel<false><<<grid, 256>>>(attnh, wouth, bout, out,
                                            M_, C_, C_, 0, 1.f);
    }
}

// round 17
// speedup vs baseline: 1.1297x; 1.1297x over previous
#include <cuda_runtime.h>
#include <cuda_fp16.h>
#include <cstdint>
#include <cstddef>

#define B_ 2
#define T_ 4096
#define C_ 768
#define H_ 12
#define D_ 64
#define M_ (B_*T_)          // 8192
#define N_QKV (3*C_)        // 2304
// softmax scale folded with log2(e) so we can use ex2
#define QSCALE (0.125f * 1.4426950408889634f)

// fp16 scratch (allocation-free requirement -> __device__ globals)
__device__ __half g_xh[(size_t)M_ * C_];
__device__ __half g_wqkvh[(size_t)C_ * N_QKV];
__device__ __half g_wouth[(size_t)C_ * C_];
__device__ __half g_qkvh[(size_t)M_ * N_QKV];   // Q part pre-scaled by QSCALE
__device__ __half g_attnh[(size_t)M_ * C_];

// ---------------------------------------------------------------------------
// Helpers
// ---------------------------------------------------------------------------
__device__ __forceinline__ void mma_f16(float* c, const uint32_t* a,
                                        uint32_t b0, uint32_t b1) {
    asm volatile(
        "mma.sync.aligned.m16n8k16.row.col.f32.f16.f16.f32 "
        "{%0,%1,%2,%3},{%4,%5,%6,%7},{%8,%9},{%0,%1,%2,%3};"
        : "+f"(c[0]), "+f"(c[1]), "+f"(c[2]), "+f"(c[3])
        : "r"(a[0]), "r"(a[1]), "r"(a[2]), "r"(a[3]), "r"(b0), "r"(b1));
}

__device__ __forceinline__ void ldsm_x4(uint32_t& r0, uint32_t& r1,
                                        uint32_t& r2, uint32_t& r3,
                                        uint32_t addr) {
    asm volatile(
        "ldmatrix.sync.aligned.m8n8.x4.shared.b16 {%0,%1,%2,%3}, [%4];"
        : "=r"(r0), "=r"(r1), "=r"(r2), "=r"(r3) : "r"(addr));
}

__device__ __forceinline__ void ldsm_x4_trans(uint32_t& r0, uint32_t& r1,
                                              uint32_t& r2, uint32_t& r3,
                                              uint32_t addr) {
    asm volatile(
        "ldmatrix.sync.aligned.m8n8.x4.trans.shared.b16 {%0,%1,%2,%3}, [%4];"
        : "=r"(r0), "=r"(r1), "=r"(r2), "=r"(r3) : "r"(addr));
}

__device__ __forceinline__ uint32_t pack_h2(float lo, float hi) {
    __half2 h = __floats2half2_rn(lo, hi);
    return *reinterpret_cast<uint32_t*>(&h);
}

__device__ __forceinline__ float fast_exp2(float x) {
    float r;
    asm("ex2.approx.ftz.f32 %0, %1;" : "=f"(r) : "f"(x));
    return r;
}

// packed fp16 helpers (softmax fast path)
__device__ __forceinline__ uint32_t hsub2(uint32_t a, uint32_t b) {
    uint32_t r;
    asm("sub.f16x2 %0, %1, %2;" : "=r"(r) : "r"(a), "r"(b));
    return r;
}
__device__ __forceinline__ uint32_t hex2_h2(uint32_t x) {
    uint32_t r;
    asm("ex2.approx.f16x2 %0, %1;" : "=r"(r) : "r"(x));
    return r;
}

__device__ __forceinline__ uint32_t smem_u32(const void* p) {
    return (uint32_t)__cvta_generic_to_shared(p);
}
// L1-preserving async copy (NOT .cg — the round-4 lesson)
__device__ __forceinline__ void cp_async16_ca(uint32_t dst, const void* src) {
    asm volatile("cp.async.ca.shared.global [%0], [%1], 16;"
                 :: "r"(dst), "l"(src));
}
__device__ __forceinline__ void cp_commit() {
    asm volatile("cp.async.commit_group;");
}
__device__ __forceinline__ void cp_wait0() {
    asm volatile("cp.async.wait_group 0;");
}

// ---------------------------------------------------------------------------
// Fused fp32 -> fp16 conversion for all three tensors (one launch)
// ---------------------------------------------------------------------------
__global__ void __launch_bounds__(256)
cvt3_f32_f16(const float* __restrict__ a, __half* __restrict__ oa, int na4,
             const float* __restrict__ b, __half* __restrict__ ob, int nb4,
             const float* __restrict__ c, __half* __restrict__ oc, int nc4)
{
    int i = blockIdx.x * blockDim.x + threadIdx.x;
    const float* in;
    __half* out;
    int off;
    if (i < na4)                  { in = a; out = oa; off = i; }
    else if (i < na4 + nb4)       { in = b; out = ob; off = i - na4; }
    else if (i < na4 + nb4 + nc4) { in = c; out = oc; off = i - na4 - nb4; }
    else return;

    float4 v = reinterpret_cast<const float4*>(in)[off];
    __half2 h0 = __floats2half2_rn(v.x, v.y);
    __half2 h1 = __floats2half2_rn(v.z, v.w);
    uint2 u;
    u.x = *reinterpret_cast<uint32_t*>(&h0);
    u.y = *reinterpret_cast<uint32_t*>(&h1);
    reinterpret_cast<uint2*>(out)[off] = u;
}

// ---------------------------------------------------------------------------
// fp16-in tensor-core GEMM with bias (round-9 proven version):
// C[M,N] = A[M,K] @ B[K,N] + bias[N]
// BM=BN=128, BK=32, 256 threads (8 warps), warp tile 64x32 (m16n8k16).
// 2-stage smem double buffer + register prefetch, 2 CTAs/SM.
// ---------------------------------------------------------------------------
template<bool HALF_OUT>
__global__ void __launch_bounds__(256, 2)
gemm_h_kernel(const __half* __restrict__ A, const __half* __restrict__ B,
              const float* __restrict__ bias, void* __restrict__ Cout,
              int M, int N, int K, int qcols, float qsc)
{
    __shared__ __half As[2][128][40];   // 20480 B
    __shared__ __half Bs[2][32][136];   // 17408 B

    const int tid = threadIdx.x;
    const int wid = tid >> 5;
    const int lane = tid & 31;
    const int g = lane >> 2;
    const int t4 = lane & 3;
    const int wm = wid >> 2;
    const int wn = wid & 3;
    const int bx = blockIdx.x, by = blockIdx.y;
    const int mrow = lane & 7;
    const int mid  = lane >> 3;

    const uint32_t abase = smem_u32(
        &As[0][wm * 64 + (mid & 1) * 8 + mrow][(mid >> 1) * 8]);
    const uint32_t bbase = smem_u32(
        &Bs[0][(mid & 1) * 8 + mrow][wn * 32 + (mid >> 1) * 8]);
    const uint32_t a_ststride = 128 * 40 * 2;
    const uint32_t b_ststride = 32 * 136 * 2;

    const int ar = tid >> 2;            // rows ar, ar+64
    const int ach = tid & 3;
    const int br = tid >> 4;            // rows br, br+16
    const int bch = tid & 15;

    const __half* aG = A + (size_t)(by * 128 + ar) * K + ach * 8;
    const __half* bG = B + (size_t)br * N + bx * 128 + bch * 8;
    const size_t aRow64 = (size_t)64 * K;
    const size_t bRow16 = (size_t)16 * N;

    uint4 pa0, pa1, pb0, pb1;
    auto ldg_slab = [&](int k0) {
        pa0 = *reinterpret_cast<const uint4*>(aG + k0);
        pa1 = *reinterpret_cast<const uint4*>(aG + aRow64 + k0);
        pb0 = *reinterpret_cast<const uint4*>(bG + (size_t)k0 * N);
        pb1 = *reinterpret_cast<const uint4*>(bG + (size_t)k0 * N + bRow16);
    };
    auto sts_slab = [&](int st) {
        *reinterpret_cast<uint4*>(&As[st][ar][ach * 8])      = pa0;
        *reinterpret_cast<uint4*>(&As[st][ar + 64][ach * 8]) = pa1;
        *reinterpret_cast<uint4*>(&Bs[st][br][bch * 8])      = pb0;
        *reinterpret_cast<uint4*>(&Bs[st][br + 16][bch * 8]) = pb1;
    };

    float acc[4][4][4];
    #pragma unroll
    for (int mt = 0; mt < 4; mt++)
        #pragma unroll
        for (int nt = 0; nt < 4; nt++)
            #pragma unroll
            for (int i = 0; i < 4; i++) acc[mt][nt][i] = 0.f;

    const int steps = K >> 5;
    ldg_slab(0);
    sts_slab(0);
    __syncthreads();

    for (int s = 0; s < steps; s++) {
        if (s + 1 < steps) ldg_slab((s + 1) << 5);

        const uint32_t ab = abase + (uint32_t)(s & 1) * a_ststride;
        const uint32_t bb = bbase + (uint32_t)(s & 1) * b_ststride;
        #pragma unroll
        for (int kk = 0; kk < 32; kk += 16) {
            uint32_t afr[4][4], bfr[4][2];
            #pragma unroll
            for (int mt = 0; mt < 4; mt++)
                ldsm_x4(afr[mt][0], afr[mt][1], afr[mt][2], afr[mt][3],
                        ab + (uint32_t)(mt * 16 * 40 + kk) * 2);
            #pragma unroll
            for (int p = 0; p < 2; p++) {
                uint32_t r0, r1, r2, r3;
                ldsm_x4_trans(r0, r1, r2, r3,
                              bb + (uint32_t)(kk * 136 + p * 16) * 2);
                bfr[2 * p][0] = r0; bfr[2 * p][1] = r1;
                bfr[2 * p + 1][0] = r2; bfr[2 * p + 1][1] = r3;
            }
            #pragma unroll
            for (int mt = 0; mt < 4; mt++)
                #pragma unroll
                for (int nt = 0; nt < 4; nt++)
                    mma_f16(acc[mt][nt], afr[mt], bfr[nt][0], bfr[nt][1]);
        }

        if (s + 1 < steps) sts_slab((s + 1) & 1);
        __syncthreads();
    }

    // ---- epilogue ----
    float osc = 1.f;
    if (HALF_OUT) osc = (bx * 128 < qcols) ? qsc : 1.f;

    #pragma unroll
    for (int nt = 0; nt < 4; nt++) {
        const int col = bx * 128 + wn * 32 + nt * 8 + 2 * t4;
        const float b0 = bias[col], b1 = bias[col + 1];
        #pragma unroll
        for (int mt = 0; mt < 4; mt++) {
            const int row = by * 128 + wm * 64 + mt * 16 + g;
            if (HALF_OUT) {
                __half* Ch = (__half*)Cout;
                uint32_t v0 = pack_h2((acc[mt][nt][0] + b0) * osc,
                                      (acc[mt][nt][1] + b1) * osc);
                uint32_t v1 = pack_h2((acc[mt][nt][2] + b0) * osc,
                                      (acc[mt][nt][3] + b1) * osc);
                *reinterpret_cast<uint32_t*>(&Ch[(size_t)row * N + col]) = v0;
                *reinterpret_cast<uint32_t*>(&Ch[(size_t)(row + 8) * N + col]) = v1;
            } else {
                float* Cf = (float*)Cout;
                float2 o0 = make_float2(acc[mt][nt][0] + b0, acc[mt][nt][1] + b1);
                float2 o1 = make_float2(acc[mt][nt][2] + b0, acc[mt][nt][3] + b1);
                *reinterpret_cast<float2*>(Cf + (size_t)row * N + col) = o0;
                *reinterpret_cast<float2*>(Cf + (size_t)(row + 8) * N + col) = o1;
            }
        }
    }
}

// ---------------------------------------------------------------------------
// Flash attention (causal), fp16 end-to-end, cp.async.ca double-buffered K/V.
// grid = (T/128, B*H), 256 threads (8 warps). Br=128, Bc=64, D=64.
// Round-14 proven version + causal last-tile skip: for the final KV tile
// (cols 64..127 of the diagonal block) warps 0-3 are fully masked -> they
// skip the compute block entirely (numerically identical: sc=1, P=0),
// freeing their SMSP issue slots for warps 4-7.
// ---------------------------------------------------------------------------
#define QH_HALFS (128 * 72)
#define KV_HALFS (64 * 72)
#define ATTN_SMEM ((QH_HALFS + 4 * KV_HALFS) * 2)

__global__ void __launch_bounds__(256)
attn_mma_kernel(const __half* __restrict__ qkvh, __half* __restrict__ outh)
{
    extern __shared__ __half smh[];
    __half* Qh = smh;                               // [128][72]
    __half* Kh = smh + QH_HALFS;                    // [2][64][72]
    __half* Vh = smh + QH_HALFS + 2 * KV_HALFS;     // [2][64][72]

    const int bh = blockIdx.y;
    const int b = bh / H_;
    const int h = bh % H_;
    const int qtile = gridDim.x - 1 - blockIdx.x;   // big tiles first
    const int tid = threadIdx.x;
    const int w = tid >> 5;
    const int lane = tid & 31;
    const int g = lane >> 2;
    const int t4 = lane & 3;
    const int mrow = lane & 7;
    const int mid  = lane >> 3;

    const uint32_t kfb = smem_u32(&Kh[((mid >> 1) * 8 + mrow) * 72 + (mid & 1) * 8]);
    const uint32_t vfb = smem_u32(&Vh[((mid & 1) * 8 + mrow) * 72 + (mid >> 1) * 8]);
    const uint32_t kvstride = KV_HALFS * 2;

    const uint32_t onesb = (g == 0) ? 0x3C003C00u : 0u;

    const int kvr = tid >> 3;
    const int kvch = tid & 7;
    const __half* kvG = qkvh + (size_t)(b * T_ + kvr) * N_QKV + h * D_ + kvch * 8;
    const size_t row32 = (size_t)32 * N_QKV;

    auto stage_kv = [&](int kbase, int st) {
        const __half* s0 = kvG + (size_t)kbase * N_QKV;
        const uint32_t kd = smem_u32(&Kh[st * KV_HALFS + kvr * 72 + kvch * 8]);
        const uint32_t vd = smem_u32(&Vh[st * KV_HALFS + kvr * 72 + kvch * 8]);
        const uint32_t roff = 32 * 72 * 2;
        cp_async16_ca(kd,        s0 + C_);
        cp_async16_ca(kd + roff, s0 + row32 + C_);
        cp_async16_ca(vd,        s0 + 2 * C_);
        cp_async16_ca(vd + roff, s0 + row32 + 2 * C_);
        cp_commit();
    };

    stage_kv(0, 0);
    #pragma unroll
    for (int i = 0; i < 4; i++) {
        const int c = tid + i * 256;
        const int r = c >> 3;
        const int ch = c & 7;
        *reinterpret_cast<uint4*>(&Qh[r * 72 + ch * 8]) =
            *reinterpret_cast<const uint4*>(
                qkvh + (size_t)(b * T_ + qtile * 128 + r) * N_QKV + h * D_ + ch * 8);
    }
    __syncthreads();

    uint32_t Qa[4][4];
    {
        const int row = w * 16;
        #pragma unroll
        for (int kc = 0; kc < 4; kc++) {
            const int k0 = kc * 16 + 2 * t4;
            Qa[kc][0] = *reinterpret_cast<const uint32_t*>(&Qh[(row + g) * 72 + k0]);
            Qa[kc][1] = *reinterpret_cast<const uint32_t*>(&Qh[(row + g + 8) * 72 + k0]);
            Qa[kc][2] = *reinterpret_cast<const uint32_t*>(&Qh[(row + g) * 72 + k0 + 8]);
            Qa[kc][3] = *reinterpret_cast<const uint32_t*>(&Qh[(row + g + 8) * 72 + k0 + 8]);
        }
    }

    float o[8][4];
    #pragma unroll
    for (int nt = 0; nt < 8; nt++)
        #pragma unroll
        for (int i = 0; i < 4; i++) o[nt][i] = 0.f;
    float la[4] = {0.f, 0.f, 0.f, 0.f};
    float m0 = -1e30f, m1 = -1e30f;

    const int q0g = qtile * 128 + w * 16 + g;
    const int ntiles = 2 * qtile + 2;

    for (int kt = 0; kt < ntiles; kt++) {
        const int kbase = kt * 64;
        cp_wait0();
        __syncthreads();
        if (kt + 1 < ntiles)
            stage_kv((kt + 1) * 64, (kt + 1) & 1);

        // Last tile (cols 64..127 of the diagonal block) is fully masked for
        // warps 0-3 (their rows end at local 63): skip compute entirely.
        // Numerically identical: all S=-inf -> mx<m -> sc=1, P=0.
        if ((kt == ntiles - 1) && (w < 4)) continue;

        const uint32_t kb = kfb + (uint32_t)(kt & 1) * kvstride;
        const uint32_t vb = vfb + (uint32_t)(kt & 1) * kvstride;

        float s_[8][4];
        #pragma unroll
        for (int nt = 0; nt < 8; nt++)
            #pragma unroll
            for (int i = 0; i < 4; i++) s_[nt][i] = 0.f;
        #pragma unroll
        for (int kc = 0; kc < 4; kc++) {
            #pragma unroll
            for (int np = 0; np < 4; np++) {
                uint32_t r0, r1, r2, r3;
                ldsm_x4(r0, r1, r2, r3,
                        kb + (uint32_t)(np * 16 * 72 + kc * 16) * 2);
                mma_f16(s_[2 * np],     Qa[kc], r0, r1);
                mma_f16(s_[2 * np + 1], Qa[kc], r2, r3);
            }
        }

        if (kbase + 63 > q0g) {
            #pragma unroll
            for (int nt = 0; nt < 8; nt++) {
                const int c0 = kbase + nt * 8 + 2 * t4;
                if (c0 > q0g)         s_[nt][0] = -1e30f;
                if (c0 + 1 > q0g)     s_[nt][1] = -1e30f;
                if (c0 > q0g + 8)     s_[nt][2] = -1e30f;
                if (c0 + 1 > q0g + 8) s_[nt][3] = -1e30f;
            }
        }

        float mx0 = -1e30f, mx1 = -1e30f;
        #pragma unroll
        for (int nt = 0; nt < 8; nt++) {
            mx0 = fmaxf(mx0, fmaxf(s_[nt][0], s_[nt][1]));
            mx1 = fmaxf(mx1, fmaxf(s_[nt][2], s_[nt][3]));
        }
        mx0 = fmaxf(mx0, __shfl_xor_sync(0xffffffff, mx0, 1));
        mx0 = fmaxf(mx0, __shfl_xor_sync(0xffffffff, mx0, 2));
        mx1 = fmaxf(mx1, __shfl_xor_sync(0xffffffff, mx1, 1));
        mx1 = fmaxf(mx1, __shfl_xor_sync(0xffffffff, mx1, 2));
        const float nm0 = fmaxf(m0, mx0), nm1 = fmaxf(m1, mx1);
        const float sc0 = fast_exp2(m0 - nm0), sc1 = fast_exp2(m1 - nm1);
        m0 = nm0; m1 = nm1;

        const uint32_t mh0 = pack_h2(m0, m0);
        const uint32_t mh1 = pack_h2(m1, m1);
        uint32_t P0[8], P1[8];
        #pragma unroll
        for (int nt = 0; nt < 8; nt++) {
            P0[nt] = hex2_h2(hsub2(pack_h2(s_[nt][0], s_[nt][1]), mh0));
            P1[nt] = hex2_h2(hsub2(pack_h2(s_[nt][2], s_[nt][3]), mh1));
        }

        la[0] *= sc0; la[1] *= sc0; la[2] *= sc1; la[3] *= sc1;
        #pragma unroll
        for (int nt = 0; nt < 8; nt++) {
            o[nt][0] *= sc0; o[nt][1] *= sc0;
            o[nt][2] *= sc1; o[nt][3] *= sc1;
        }

        #pragma unroll
        for (int kc = 0; kc < 4; kc++) {
            uint32_t pa[4];
            pa[0] = P0[2 * kc];
            pa[1] = P1[2 * kc];
            pa[2] = P0[2 * kc + 1];
            pa[3] = P1[2 * kc + 1];
            #pragma unroll
            for (int p = 0; p < 4; p++) {
                uint32_t v0, v1, v2, v3;
                ldsm_x4_trans(v0, v1, v2, v3,
                              vb + (uint32_t)(kc * 16 * 72 + p * 16) * 2);
                mma_f16(o[2 * p],     pa, v0, v1);
                mma_f16(o[2 * p + 1], pa, v2, v3);
            }
            mma_f16(la, pa, onesb, onesb);
        }
    }

    const int qlead = lane & 28;
    const float l0 = __shfl_sync(0xffffffff, la[0], qlead);
    const float l1 = __shfl_sync(0xffffffff, la[2], qlead);
    const float inv0 = 1.f / l0, inv1 = 1.f / l1;
    const size_t row0 = (size_t)(b * T_ + qtile * 128 + w * 16 + g);
    const size_t row1 = row0 + 8;
    #pragma unroll
    for (int nt = 0; nt < 8; nt++) {
        const int col = h * D_ + nt * 8 + 2 * t4;
        uint32_t v0 = pack_h2(o[nt][0] * inv0, o[nt][1] * inv0);
        uint32_t v1 = pack_h2(o[nt][2] * inv1, o[nt][3] * inv1);
        *reinterpret_cast<uint32_t*>(&outh[row0 * C_ + col]) = v0;
        *reinterpret_cast<uint32_t*>(&outh[row1 * C_ + col]) = v1;
    }
}

// ---------------------------------------------------------------------------
// Launch
// ---------------------------------------------------------------------------
extern "C" void kernel_launch(void* const* d_in, const int* in_sizes, int n_in,
                              void* d_out, int out_size)
{
    const float* x    = (const float*)d_in[0];
    const float* Wqkv = (const float*)d_in[1];
    const float* bqkv = (const float*)d_in[2];
    const float* Wout = (const float*)d_in[3];
    const float* bout = (const float*)d_in[4];
    float* out = (float*)d_out;

    __half *xh, *wqkvh, *wouth, *qkvh, *attnh;
    cudaGetSymbolAddress((void**)&xh,    g_xh);
    cudaGetSymbolAddress((void**)&wqkvh, g_wqkvh);
    cudaGetSymbolAddress((void**)&wouth, g_wouth);
    cudaGetSymbolAddress((void**)&qkvh,  g_qkvh);
    cudaGetSymbolAddress((void**)&attnh, g_attnh);

    cudaFuncSetAttribute(attn_mma_kernel,
                         cudaFuncAttributeMaxDynamicSharedMemorySize, ATTN_SMEM);

    // 0) fp32 -> fp16 conversions (single fused launch)
    {
        const int n0 = M_ * C_ / 4;
        const int n1 = C_ * N_QKV / 4;
        const int n2 = C_ * C_ / 4;
        const int ntot = n0 + n1 + n2;
        cvt3_f32_f16<<<(ntot + 255) / 256, 256>>>(x, xh, n0,
                                                  Wqkv, wqkvh, n1,
                                                  Wout, wouth, n2);
    }

    // 1) QKV projection (fp16 out, Q columns pre-scaled by QSCALE)
    {
        dim3 grid(N_QKV / 128, M_ / 128);
        gemm_h_kernel<true><<<grid, 256>>>(xh, wqkvh, bqkv, qkvh,
                                           M_, N_QKV, C_, C_, (float)QSCALE);
    }
    // 2) Causal attention (flash, fp16 tensor cores, fp16 out)
    {
        dim3 grid(T_ / 128, B_ * H_);
        attn_mma_kernel<<<grid, 256, ATTN_SMEM>>>(qkvh, attnh);
    }
    // 3) Output projection (fp32 out)
    {
        dim3 grid(C_ / 128, M_ / 128);
        gemm_h_kernel<false><<<grid, 256>>>(attnh, wouth, bout, out,
                                            M_, C_, C_, 0, 1.f);
    }
}